// round 14
// baseline (speedup 1.0000x reference)
#include <cuda_runtime.h>
#include <cuda_fp16.h>
#include <cstdint>

#define D      512
#define WGRP   1536
#define MGRP   64
#define TB     30000
#define TBP    30080
#define KTOP   5
#define NRT    12
#define NCT    235
#define BK     128                    // int8 elements per k-chunk (128 B/row)
#define NCH    4                      // 512 / 128
#define PLANE_B 16384                 // 128 rows x 128 B (int8)
#define STAGE_B (2 * PLANE_B)         // 32 KB (A, B)
#define NSTAGE 3
#define DSMEM_TOTAL (NSTAGE * STAGE_B)  // 96 KB
#define MARGIN 9e-3f
#define MAXCAND 64
#define MAXTILE 64

// ---------------- scratch ----------------
__device__ int8_t g_Ai[WGRP * D];
__device__ int8_t g_Bi[TBP * D];
__device__ float  g_sa[WGRP];              // A row quant scale
__device__ float  g_sbi[TBP];              // B row quant scale * inv-norm
__device__ float  g_a[WGRP * D];
__device__ float  g_invt[TBP];
__device__ __half g_cos[(size_t)WGRP * TBP];
__device__ float  g_tmax[(size_t)WGRP * NCT];   // [row][tile]
__device__ float  g_topk[WGRP * D];

typedef unsigned long long ull;

// ---------------- PTX helpers (sm_80-era only) ----------------
__device__ __forceinline__ uint32_t smem_u32(const void* p) {
    uint32_t a;
    asm("{ .reg .u64 t; cvta.to.shared.u64 t, %1; cvt.u32.u64 %0, t; }" : "=r"(a) : "l"(p));
    return a;
}
__device__ __forceinline__ void cp16(uint32_t dst, const void* src) {
    asm volatile("cp.async.cg.shared.global [%0], [%1], 16;" :: "r"(dst), "l"(src));
}
__device__ __forceinline__ void cp_commit() {
    asm volatile("cp.async.commit_group;" ::: "memory");
}
template <int N>
__device__ __forceinline__ void cp_wait() {
    asm volatile("cp.async.wait_group %0;" :: "n"(N) : "memory");
}
__device__ __forceinline__ void ldsm_x4(uint32_t (&r)[4], uint32_t addr) {
    asm volatile("ldmatrix.sync.aligned.m8n8.x4.shared.b16 {%0,%1,%2,%3}, [%4];"
                 : "=r"(r[0]), "=r"(r[1]), "=r"(r[2]), "=r"(r[3]) : "r"(addr));
}
__device__ __forceinline__ void imma16832(int (&d)[4], const uint32_t (&a)[4], const uint32_t* b) {
    asm volatile(
        "mma.sync.aligned.m16n8k32.row.col.s32.s8.s8.s32 "
        "{%0,%1,%2,%3}, {%4,%5,%6,%7}, {%8,%9}, {%0,%1,%2,%3};"
        : "+r"(d[0]), "+r"(d[1]), "+r"(d[2]), "+r"(d[3])
        : "r"(a[0]), "r"(a[1]), "r"(a[2]), "r"(a[3]), "r"(b[0]), "r"(b[1]));
}
__device__ __forceinline__ ull pk2(float lo, float hi) {
    ull r; asm("mov.b64 %0, {%1, %2};" : "=l"(r) : "f"(lo), "f"(hi)); return r;
}
__device__ __forceinline__ void unpk2(ull v, float& lo, float& hi) {
    asm("mov.b64 {%0, %1}, %2;" : "=f"(lo), "=f"(hi) : "l"(v));
}
__device__ __forceinline__ void fma2(ull& d, ull a, ull b) {
    asm("fma.rn.f32x2 %0, %1, %2, %0;" : "+l"(d) : "l"(a), "l"(b));
}

// ---------------- top-5 values-only insert ----------------
__device__ __forceinline__ void ins5v(float (&tv)[5], float v) {
    if (v > tv[4]) {
#pragma unroll
        for (int s = 0; s < 5; s++) {
            float hi = fmaxf(tv[s], v);
            float lo = fminf(tv[s], v);
            tv[s] = hi; v = lo;
        }
    }
}

// ---------------- Kernel A: group mean + normalize -> fp32 + int8 quant ----------------
__global__ __launch_bounds__(128)
void k_avg_split(const float* __restrict__ x) {
    int g = blockIdx.x, t = threadIdx.x;
    const float* p = x + (size_t)g * (MGRP * D) + t * 4;
    float4 s0 = make_float4(0.f, 0.f, 0.f, 0.f), s1 = s0;
#pragma unroll 4
    for (int r = 0; r < MGRP; r += 2) {
        float4 a  = *(const float4*)(p + (size_t)r * D);
        float4 b2 = *(const float4*)(p + (size_t)(r + 1) * D);
        s0.x += a.x;  s0.y += a.y;  s0.z += a.z;  s0.w += a.w;
        s1.x += b2.x; s1.y += b2.y; s1.z += b2.z; s1.w += b2.w;
    }
    float4 m;
    m.x = (s0.x + s1.x) * (1.0f / 64.0f);
    m.y = (s0.y + s1.y) * (1.0f / 64.0f);
    m.z = (s0.z + s1.z) * (1.0f / 64.0f);
    m.w = (s0.w + s1.w) * (1.0f / 64.0f);
    float ss = m.x * m.x + m.y * m.y + m.z * m.z + m.w * m.w;
    __shared__ float red[128];
    red[t] = ss;
    __syncthreads();
    for (int o = 64; o > 0; o >>= 1) {
        if (t < o) red[t] += red[t + o];
        __syncthreads();
    }
    float inv = 1.0f / fmaxf(sqrtf(red[0]), 1e-8f);
    float v[4] = {m.x * inv, m.y * inv, m.z * inv, m.w * inv};
    size_t base = (size_t)g * D + t * 4;
    *(float4*)(g_a + base) = make_float4(v[0], v[1], v[2], v[3]);
    // row absmax
    float am = fmaxf(fmaxf(fabsf(v[0]), fabsf(v[1])), fmaxf(fabsf(v[2]), fabsf(v[3])));
    __syncthreads();
    red[t] = am;
    __syncthreads();
    for (int o = 64; o > 0; o >>= 1) {
        if (t < o) red[t] = fmaxf(red[t], red[t + o]);
        __syncthreads();
    }
    float s = fmaxf(red[0], 1e-20f) / 127.0f;
    float rs = 1.0f / s;
    char4 q;
    q.x = (char)__float2int_rn(v[0] * rs);
    q.y = (char)__float2int_rn(v[1] * rs);
    q.z = (char)__float2int_rn(v[2] * rs);
    q.w = (char)__float2int_rn(v[3] * rs);
    *(char4*)(g_Ai + base) = q;
    if (t == 0) g_sa[g] = s;
}

// ---------------- Kernel B: text-bank inv-norm + int8 quant (padded) ----------------
__global__ __launch_bounds__(128)
void k_bsplit(const float* __restrict__ tb) {
    int row = blockIdx.x, t = threadIdx.x;
    size_t base = (size_t)row * D + t * 4;
    __shared__ float wsum[4], wmax[4];
    if (row < TB) {
        float4 v4 = *(const float4*)(tb + base);
        float v[4] = {v4.x, v4.y, v4.z, v4.w};
        float ss = v[0] * v[0] + v[1] * v[1] + v[2] * v[2] + v[3] * v[3];
        float am = fmaxf(fmaxf(fabsf(v[0]), fabsf(v[1])), fmaxf(fabsf(v[2]), fabsf(v[3])));
#pragma unroll
        for (int o = 16; o > 0; o >>= 1) {
            ss += __shfl_xor_sync(0xffffffffu, ss, o);
            am = fmaxf(am, __shfl_xor_sync(0xffffffffu, am, o));
        }
        if ((t & 31) == 0) { wsum[t >> 5] = ss; wmax[t >> 5] = am; }
        __syncthreads();
        float tot = wsum[0] + wsum[1] + wsum[2] + wsum[3];
        float amax = fmaxf(fmaxf(wmax[0], wmax[1]), fmaxf(wmax[2], wmax[3]));
        float invt = 1.0f / fmaxf(sqrtf(tot), 1e-8f);
        float s = fmaxf(amax, 1e-20f) / 127.0f;
        if (t == 0) { g_invt[row] = invt; g_sbi[row] = s * invt; }
        float rs = 1.0f / s;
        char4 q;
        q.x = (char)__float2int_rn(v[0] * rs);
        q.y = (char)__float2int_rn(v[1] * rs);
        q.z = (char)__float2int_rn(v[2] * rs);
        q.w = (char)__float2int_rn(v[3] * rs);
        *(char4*)(g_Bi + base) = q;
    } else {
        if (t == 0) { g_invt[row] = 0.0f; g_sbi[row] = 0.0f; }
        *(char4*)(g_Bi + base) = make_char4(0, 0, 0, 0);
    }
}

// ---------------- Kernel C: int8 IMMA GEMM -> scaled fp16 cos + per-tile row max ----------------
__global__ __launch_bounds__(256, 2)
void k_gemm() {
    extern __shared__ char dsm[];
    __shared__ float sInv[128];   // s_b * invt per col
    __shared__ float sA[128];     // s_a per row
    __shared__ float smax[128][4];

    const int tid = threadIdx.x;
    const int wid = tid >> 5, lane = tid & 31;
    const int wr = wid >> 2, wc = wid & 3;          // 2 x 4 warp grid, 64x32 warp tiles
    const int rowblk = blockIdx.x, coltile = blockIdx.y;

    if (tid < 128) {
        sInv[tid] = g_sbi[coltile * 128 + tid];
        sA[tid]   = g_sa[rowblk * 128 + tid];
    }

    const uint32_t sbase = smem_u32(dsm);

    const int r0 = tid >> 3;
    const int cch = tid & 7;
    const int8_t* gA = g_Ai + (size_t)(rowblk * 128 + r0) * D + cch * 16;
    const int8_t* gB = g_Bi + (size_t)(coltile * 128 + r0) * D + cch * 16;

    auto load_chunk = [&](int c, int buf) {
        uint32_t st = sbase + buf * STAGE_B;
        const int8_t* a = gA + c * BK;
        const int8_t* b = gB + c * BK;
#pragma unroll
        for (int i = 0; i < 4; i++) {
            int row = r0 + 32 * i;
            uint32_t soff = (uint32_t)row * 128 + ((uint32_t)(cch ^ (row & 7))) * 16;
            cp16(st + soff, a + (size_t)(32 * i) * D);
            cp16(st + PLANE_B + soff, b + (size_t)(32 * i) * D);
        }
        cp_commit();
    };

    load_chunk(0, 0);
    load_chunk(1, 1);

    int acc[4][4][4];
#pragma unroll
    for (int mt = 0; mt < 4; mt++)
#pragma unroll
        for (int nt = 0; nt < 4; nt++)
#pragma unroll
            for (int q = 0; q < 4; q++) acc[mt][nt][q] = 0;

    const int a_m  = wr * 64 + (lane & 15);
    const int a_kh = lane >> 4;
    const int b_n  = wc * 32 + (lane & 7) + ((lane >> 4) & 1) * 8;
    const int b_kh = (lane >> 3) & 1;

    for (int c = 0; c < NCH; c++) {
        if (c < NCH - 1) cp_wait<1>(); else cp_wait<0>();
        __syncthreads();
        if (c + 2 < NCH) load_chunk(c + 2, (c + 2) % 3);

        const uint32_t st = sbase + (c % 3) * STAGE_B;
#pragma unroll
        for (int ks = 0; ks < 4; ks++) {          // k32 steps within 128-B chunk
            uint32_t af[4][4];
#pragma unroll
            for (int mt = 0; mt < 4; mt++) {
                int m = a_m + mt * 16;
                uint32_t chunk = (uint32_t)(ks * 2 + a_kh);
                ldsm_x4(af[mt], st + (uint32_t)m * 128 + (chunk ^ (m & 7)) * 16);
            }
            uint32_t bf[8];
#pragma unroll
            for (int ntp = 0; ntp < 2; ntp++) {
                int n = b_n + ntp * 16;
                uint32_t chunk = (uint32_t)(ks * 2 + b_kh);
                uint32_t r4[4];
                ldsm_x4(r4, st + PLANE_B + (uint32_t)n * 128 + (chunk ^ (n & 7)) * 16);
                bf[ntp * 4 + 0] = r4[0]; bf[ntp * 4 + 1] = r4[1];
                bf[ntp * 4 + 2] = r4[2]; bf[ntp * 4 + 3] = r4[3];
            }
#pragma unroll
            for (int mt = 0; mt < 4; mt++)
#pragma unroll
                for (int nt = 0; nt < 4; nt++)
                    imma16832(acc[mt][nt], af[mt], &bf[nt * 2]);
        }
    }
    __syncthreads();

    // ---- epilogue: scale (sA*sInv), store fp16, per-row tile max ----
    const int rb = wr * 64 + (lane >> 2);
    const int cb = wc * 32 + (lane & 3) * 2;
    const size_t grow0 = (size_t)(rowblk * 128);
    const int gcol0 = coltile * 128;

    float rmaxA[4], rmaxB[4];
#pragma unroll
    for (int mt = 0; mt < 4; mt++) { rmaxA[mt] = -1e30f; rmaxB[mt] = -1e30f; }

#pragma unroll
    for (int mt = 0; mt < 4; mt++) {
        float sr0 = sA[rb + mt * 16], sr1 = sA[rb + mt * 16 + 8];
#pragma unroll
        for (int nt = 0; nt < 4; nt++) {
            int r = rb + mt * 16, cc = cb + nt * 8;
            int gc0 = gcol0 + cc, gc1 = gc0 + 1;
            float i0 = sInv[cc], i1 = sInv[cc + 1];
            float v0 = (float)acc[mt][nt][0] * (sr0 * i0);
            float v1 = (float)acc[mt][nt][1] * (sr0 * i1);
            float v2 = (float)acc[mt][nt][2] * (sr1 * i0);
            float v3 = (float)acc[mt][nt][3] * (sr1 * i1);
            *(__half2*)&g_cos[(grow0 + r)     * TBP + gc0] = __floats2half2_rn(v0, v1);
            *(__half2*)&g_cos[(grow0 + r + 8) * TBP + gc0] = __floats2half2_rn(v2, v3);
            float m0 = (gc0 < TB) ? v0 : -1e30f;
            float m1 = (gc1 < TB) ? v1 : -1e30f;
            float m2 = (gc0 < TB) ? v2 : -1e30f;
            float m3 = (gc1 < TB) ? v3 : -1e30f;
            rmaxA[mt] = fmaxf(rmaxA[mt], fmaxf(m0, m1));
            rmaxB[mt] = fmaxf(rmaxB[mt], fmaxf(m2, m3));
        }
    }
#pragma unroll
    for (int o = 1; o <= 2; o <<= 1) {
#pragma unroll
        for (int mt = 0; mt < 4; mt++) {
            rmaxA[mt] = fmaxf(rmaxA[mt], __shfl_xor_sync(0xffffffffu, rmaxA[mt], o));
            rmaxB[mt] = fmaxf(rmaxB[mt], __shfl_xor_sync(0xffffffffu, rmaxB[mt], o));
        }
    }
    if ((lane & 3) == 0) {
        int rr = wr * 64 + (lane >> 2);
#pragma unroll
        for (int mt = 0; mt < 4; mt++) {
            smax[rr + mt * 16][wc]     = rmaxA[mt];
            smax[rr + mt * 16 + 8][wc] = rmaxB[mt];
        }
    }
    __syncthreads();
    if (tid < 128) {
        float m = fmaxf(fmaxf(smax[tid][0], smax[tid][1]), fmaxf(smax[tid][2], smax[tid][3]));
        g_tmax[(grow0 + tid) * NCT + coltile] = m;
    }
}

// ---------------- Kernel D: select (two-level threshold, fast path) ----------------
__global__ __launch_bounds__(128)
void k_select(const float* __restrict__ tb) {
    const int row = blockIdx.x, t = threadIdx.x;
    const int lane = t & 31, w = t >> 5;

    __shared__ float  s_red[4][5];
    __shared__ int    s_redi[4][5];
    __shared__ int    s_t5[5];
    __shared__ float  s_thresh;
    __shared__ int    s_ntile, s_cnt;
    __shared__ int    s_tiles[MAXTILE];
    __shared__ int    s_cand[MAXCAND];
    __shared__ double s_cval[MAXCAND];
    __shared__ int    s_sel[KTOP];

    // ---- phase 1: load tmax + per-warp lex top-5 ----
    const float* tmrow = g_tmax + (size_t)row * NCT;
    float tm0 = (t < NCT) ? tmrow[t] : -1e30f;
    float tm1 = (t + 128 < NCT) ? tmrow[t + 128] : -1e30f;
    {
        float v0 = tm0, v1 = tm1;
        int   i0 = t,   i1 = t + 128;
#pragma unroll
        for (int s = 0; s < KTOP; s++) {
            float bv; int bc;
            if (v0 > v1 || (v0 == v1 && i0 < i1)) { bv = v0; bc = i0; }
            else                                   { bv = v1; bc = i1; }
#pragma unroll
            for (int o = 16; o > 0; o >>= 1) {
                float ov = __shfl_xor_sync(0xffffffffu, bv, o);
                int   oc = __shfl_xor_sync(0xffffffffu, bc, o);
                if (ov > bv || (ov == bv && oc < bc)) { bv = ov; bc = oc; }
            }
            if (lane == 0) { s_red[w][s] = bv; s_redi[w][s] = bc; }
            if (i0 == bc) v0 = -1e30f;
            if (i1 == bc) v1 = -1e30f;
        }
    }
    if (t == 0) { s_ntile = 0; s_cnt = 0; }
    __syncthreads();

    // ---- phase 1b: warp 0 merges -> top-5 tiles ----
    if (w == 0) {
        float v = (lane < 20) ? s_red[lane / 5][lane % 5] : -1e30f;
        int   c = (lane < 20) ? s_redi[lane / 5][lane % 5] : 0x7fffffff;
#pragma unroll
        for (int s = 0; s < KTOP; s++) {
            float bv = v; int bc = c;
#pragma unroll
            for (int o = 16; o > 0; o >>= 1) {
                float ov = __shfl_xor_sync(0xffffffffu, bv, o);
                int   oc = __shfl_xor_sync(0xffffffffu, bc, o);
                if (ov > bv || (ov == bv && oc < bc)) { bv = ov; bc = oc; }
            }
            if (lane == 0) s_t5[s] = bc;
            if (c == bc) v = -1e30f;
        }
    }
    __syncthreads();

    // ---- phase 2: scan 5 best tiles -> v5 (5th-largest stored within them) ----
    const __half* crow = g_cos + (size_t)row * TBP;
    {
        float tv[5] = {-1e30f, -1e30f, -1e30f, -1e30f, -1e30f};
#pragma unroll
        for (int r = 0; r < 5; r++) {
            int col = s_t5[r] * 128 + t;
            float v = (col < TB) ? __half2float(crow[col]) : -1e30f;
            ins5v(tv, v);
        }
#pragma unroll
        for (int o = 16; o > 0; o >>= 1) {
            float ov[5];
#pragma unroll
            for (int q = 0; q < 5; q++) ov[q] = __shfl_xor_sync(0xffffffffu, tv[q], o);
#pragma unroll
            for (int q = 0; q < 5; q++) ins5v(tv, ov[q]);
        }
        if (lane == 0) {
#pragma unroll
            for (int q = 0; q < 5; q++) s_red[w][q] = tv[q];
        }
    }
    __syncthreads();
    if (t == 0) {
        float mv[5] = {-1e30f, -1e30f, -1e30f, -1e30f, -1e30f};
#pragma unroll
        for (int ww = 0; ww < 4; ww++)
#pragma unroll
            for (int q = 0; q < 5; q++) ins5v(mv, s_red[ww][q]);
        s_thresh = mv[4] - MARGIN;
    }
    __syncthreads();
    const float thresh = s_thresh;

    // ---- phase 3: qualifying tiles ----
    if (tm0 >= thresh) {
        int p = atomicAdd(&s_ntile, 1);
        if (p < MAXTILE) s_tiles[p] = t;
    }
    if (tm1 >= thresh) {
        int p = atomicAdd(&s_ntile, 1);
        if (p < MAXTILE) s_tiles[p] = t + 128;
    }
    __syncthreads();
    const int ntile = min(s_ntile, MAXTILE);

    // ---- phase 4: scan qualifying tiles for candidates ----
    for (int j = t; j < ntile * 128; j += 128) {
        int col = s_tiles[j >> 7] * 128 + (j & 127);
        if (col < TB) {
            float v = __half2float(crow[col]);
            if (v >= thresh) {
                int p = atomicAdd(&s_cnt, 1);
                if (p < MAXCAND) s_cand[p] = col;
            }
        }
    }
    __syncthreads();
    const int ncand = min(s_cnt, MAXCAND);

    if (ncand > KTOP) {
        // ---- phase 5: exact rescore (double), warp per candidate ----
        const float* arow = g_a + (size_t)row * D;
        for (int ci = w; ci < ncand; ci += 4) {
            int c = s_cand[ci];
            const float* trow = tb + (size_t)c * D;
            double acc = 0.0;
#pragma unroll
            for (int j = 0; j < 16; j++) {
                int idx = lane + 32 * j;
                acc += (double)arow[idx] * (double)trow[idx];
            }
#pragma unroll
            for (int o = 16; o > 0; o >>= 1) acc += __shfl_xor_sync(0xffffffffu, acc, o);
            if (lane == 0) s_cval[ci] = acc * (double)g_invt[c];
        }
        __syncthreads();

        // ---- phase 6: warp-0 butterfly lex top-5 ----
        if (w == 0) {
            double v0 = (lane < ncand) ? s_cval[lane] : -1e300;
            int    c0 = (lane < ncand) ? s_cand[lane] : 0x7fffffff;
            double v1 = (lane + 32 < ncand) ? s_cval[lane + 32] : -1e300;
            int    c1 = (lane + 32 < ncand) ? s_cand[lane + 32] : 0x7fffffff;
#pragma unroll
            for (int s = 0; s < KTOP; s++) {
                double bv; int bc;
                if (v0 > v1 || (v0 == v1 && c0 < c1)) { bv = v0; bc = c0; }
                else                                  { bv = v1; bc = c1; }
#pragma unroll
                for (int o = 16; o > 0; o >>= 1) {
                    double ov = __shfl_xor_sync(0xffffffffu, bv, o);
                    int    oc = __shfl_xor_sync(0xffffffffu, bc, o);
                    if (ov > bv || (ov == bv && oc < bc)) { bv = ov; bc = oc; }
                }
                if (lane == 0) s_sel[s] = bc;
                if (c0 == bc) v0 = -1e300;
                if (c1 == bc) v1 = -1e300;
            }
        }
    } else {
        if (t < KTOP) s_sel[t] = s_cand[t];
    }
    __syncthreads();

    // ---- phase 7: gather + mean ----
    int c0 = s_sel[0], c1 = s_sel[1], c2 = s_sel[2], c3 = s_sel[3], c4 = s_sel[4];
    {
        int idx = t * 4;
        float4 v0 = *(const float4*)(tb + (size_t)c0 * D + idx);
        float4 v1 = *(const float4*)(tb + (size_t)c1 * D + idx);
        float4 v2 = *(const float4*)(tb + (size_t)c2 * D + idx);
        float4 v3 = *(const float4*)(tb + (size_t)c3 * D + idx);
        float4 v4 = *(const float4*)(tb + (size_t)c4 * D + idx);
        float4 s;
        s.x = (v0.x + v1.x + v2.x + v3.x + v4.x) * 0.2f;
        s.y = (v0.y + v1.y + v2.y + v3.y + v4.y) * 0.2f;
        s.z = (v0.z + v1.z + v2.z + v3.z + v4.z) * 0.2f;
        s.w = (v0.w + v1.w + v2.w + v3.w + v4.w) * 0.2f;
        *(float4*)(g_topk + (size_t)row * D + idx) = s;
    }
}

// ---------------- Kernel E: out = topk_avg @ W^T + b (packed f32x2 FMA) ----------------
__global__ __launch_bounds__(256)
void k_out(const float* __restrict__ W, const float* __restrict__ bias, float* __restrict__ out) {
    __shared__ float As[16][68];
    __shared__ float Ws[16][68];
    int tid = threadIdx.x;
    int tx = tid & 15, ty = tid >> 4;
    int r0 = blockIdx.x * 64, o0 = blockIdx.y * 64;
    int lr = tid >> 2, k4 = tid & 3;
    const float* Ap = g_topk + (size_t)(r0 + lr) * D + k4 * 4;
    const float* Wp = W + (size_t)(o0 + lr) * D + k4 * 4;
    ull acc2[4][2];
#pragma unroll
    for (int i = 0; i < 4; i++) { acc2[i][0] = 0ull; acc2[i][1] = 0ull; }
    float4 ra = *(const float4*)Ap;
    float4 rw = *(const float4*)Wp;
    for (int kb = 0; kb < 32; kb++) {
        As[k4 * 4 + 0][lr] = ra.x; As[k4 * 4 + 1][lr] = ra.y;
        As[k4 * 4 + 2][lr] = ra.z; As[k4 * 4 + 3][lr] = ra.w;
        Ws[k4 * 4 + 0][lr] = rw.x; Ws[k4 * 4 + 1][lr] = rw.y;
        Ws[k4 * 4 + 2][lr] = rw.z; Ws[k4 * 4 + 3][lr] = rw.w;
        __syncthreads();
        if (kb + 1 < 32) {
            ra = *(const float4*)(Ap + (kb + 1) * 16);
            rw = *(const float4*)(Wp + (kb + 1) * 16);
        }
#pragma unroll
        for (int k = 0; k < 16; k++) {
            float4 a = *(const float4*)&As[k][ty * 4];
            float4 w = *(const float4*)&Ws[k][tx * 4];
            ull w01 = pk2(w.x, w.y), w23 = pk2(w.z, w.w);
            float av[4] = {a.x, a.y, a.z, a.w};
#pragma unroll
            for (int i = 0; i < 4; i++) {
                ull ai = pk2(av[i], av[i]);
                fma2(acc2[i][0], ai, w01);
                fma2(acc2[i][1], ai, w23);
            }
        }
        __syncthreads();
    }
#pragma unroll
    for (int i = 0; i < 4; i++) {
        float a0, a1, a2, a3;
        unpk2(acc2[i][0], a0, a1);
        unpk2(acc2[i][1], a2, a3);
        float accr[4] = {a0, a1, a2, a3};
#pragma unroll
        for (int jj = 0; jj < 4; jj++) {
            float bj = bias[o0 + tx * 4 + jj];
            out[(size_t)(r0 + ty * 4 + i) * D + o0 + tx * 4 + jj] = accr[jj] + bj;
        }
    }
}

extern "C" void kernel_launch(void* const* d_in, const int* in_sizes, int n_in,
                              void* d_out, int out_size) {
    const float* x  = (const float*)d_in[0];
    const float* tb = (const float*)d_in[1];
    const float* W  = (const float*)d_in[2];
    const float* b  = (const float*)d_in[3];
    float* out = (float*)d_out;

    cudaFuncSetAttribute(k_gemm, cudaFuncAttributeMaxDynamicSharedMemorySize, DSMEM_TOTAL);

    k_avg_split<<<WGRP, 128>>>(x);
    k_bsplit<<<TBP, 128>>>(tb);
    k_gemm<<<dim3(NRT, NCT), 256, DSMEM_TOTAL>>>();
    k_select<<<WGRP, 128>>>(tb);
    k_out<<<dim3(WGRP / 64, D / 64), 256>>>(W, b, out);
}

// round 15
// speedup vs baseline: 1.8654x; 1.8654x over previous
#include <cuda_runtime.h>
#include <cuda_fp16.h>
#include <cstdint>

#define D      512
#define WGRP   1536
#define MGRP   64
#define TB     30000
#define TBP    30080
#define KTOP   5
#define NRT    12
#define NCT    235
#define BK     64
#define NCH    8
#define PLANE_B 16384                 // 128 rows x 128 B (fp16)
#define STAGE_B (2 * PLANE_B)         // 32 KB (A, B)
#define NSTAGE 3
#define DSMEM_TOTAL (NSTAGE * STAGE_B)  // 96 KB
#define MARGIN 1.5e-3f
#define MAXCAND 64
#define MAXTILE 64

// ---------------- scratch ----------------
__device__ __half g_Ah[WGRP * D];
__device__ __half g_Bh[TBP * D];
__device__ float  g_a[WGRP * D];
__device__ float  g_invt[TBP];
__device__ __half g_cos[(size_t)WGRP * TBP];
__device__ float  g_tmax[(size_t)WGRP * NCT];   // [row][tile]
__device__ float  g_topk[WGRP * D];

typedef unsigned long long ull;

// ---------------- PTX helpers (sm_80-era only) ----------------
__device__ __forceinline__ uint32_t smem_u32(const void* p) {
    uint32_t a;
    asm("{ .reg .u64 t; cvta.to.shared.u64 t, %1; cvt.u32.u64 %0, t; }" : "=r"(a) : "l"(p));
    return a;
}
__device__ __forceinline__ void cp16(uint32_t dst, const void* src) {
    asm volatile("cp.async.cg.shared.global [%0], [%1], 16;" :: "r"(dst), "l"(src));
}
__device__ __forceinline__ void cp_commit() {
    asm volatile("cp.async.commit_group;" ::: "memory");
}
template <int N>
__device__ __forceinline__ void cp_wait() {
    asm volatile("cp.async.wait_group %0;" :: "n"(N) : "memory");
}
__device__ __forceinline__ void ldsm_x4(uint32_t (&r)[4], uint32_t addr) {
    asm volatile("ldmatrix.sync.aligned.m8n8.x4.shared.b16 {%0,%1,%2,%3}, [%4];"
                 : "=r"(r[0]), "=r"(r[1]), "=r"(r[2]), "=r"(r[3]) : "r"(addr));
}
__device__ __forceinline__ void mma16816(float (&d)[4], const uint32_t (&a)[4], const uint32_t* b) {
    asm volatile(
        "mma.sync.aligned.m16n8k16.row.col.f32.f16.f16.f32 "
        "{%0,%1,%2,%3}, {%4,%5,%6,%7}, {%8,%9}, {%0,%1,%2,%3};"
        : "+f"(d[0]), "+f"(d[1]), "+f"(d[2]), "+f"(d[3])
        : "r"(a[0]), "r"(a[1]), "r"(a[2]), "r"(a[3]), "r"(b[0]), "r"(b[1]));
}
__device__ __forceinline__ ull pk2(float lo, float hi) {
    ull r; asm("mov.b64 %0, {%1, %2};" : "=l"(r) : "f"(lo), "f"(hi)); return r;
}
__device__ __forceinline__ void unpk2(ull v, float& lo, float& hi) {
    asm("mov.b64 {%0, %1}, %2;" : "=f"(lo), "=f"(hi) : "l"(v));
}
__device__ __forceinline__ void fma2(ull& d, ull a, ull b) {
    asm("fma.rn.f32x2 %0, %1, %2, %0;" : "+l"(d) : "l"(a), "l"(b));
}

// ---------------- top-5 values-only insert ----------------
__device__ __forceinline__ void ins5v(float (&tv)[5], float v) {
    if (v > tv[4]) {
#pragma unroll
        for (int s = 0; s < 5; s++) {
            float hi = fmaxf(tv[s], v);
            float lo = fminf(tv[s], v);
            tv[s] = hi; v = lo;
        }
    }
}

// ---------------- Kernel AB (fused prep): blocks [0,WGRP) do A, [WGRP,WGRP+TBP) do B ----------------
__global__ __launch_bounds__(128)
void k_prep(const float* __restrict__ x, const float* __restrict__ tb) {
    int t = threadIdx.x;
    if (blockIdx.x < WGRP) {
        // ---- A side: group mean + normalize -> fp32 + fp16 ----
        int g = blockIdx.x;
        const float* p = x + (size_t)g * (MGRP * D) + t * 4;
        float4 s0 = make_float4(0.f, 0.f, 0.f, 0.f), s1 = s0;
#pragma unroll 4
        for (int r = 0; r < MGRP; r += 2) {
            float4 a  = *(const float4*)(p + (size_t)r * D);
            float4 b2 = *(const float4*)(p + (size_t)(r + 1) * D);
            s0.x += a.x;  s0.y += a.y;  s0.z += a.z;  s0.w += a.w;
            s1.x += b2.x; s1.y += b2.y; s1.z += b2.z; s1.w += b2.w;
        }
        float4 m;
        m.x = (s0.x + s1.x) * (1.0f / 64.0f);
        m.y = (s0.y + s1.y) * (1.0f / 64.0f);
        m.z = (s0.z + s1.z) * (1.0f / 64.0f);
        m.w = (s0.w + s1.w) * (1.0f / 64.0f);
        float ss = m.x * m.x + m.y * m.y + m.z * m.z + m.w * m.w;
        __shared__ float red[128];
        red[t] = ss;
        __syncthreads();
        for (int o = 64; o > 0; o >>= 1) {
            if (t < o) red[t] += red[t + o];
            __syncthreads();
        }
        float inv = 1.0f / fmaxf(sqrtf(red[0]), 1e-8f);
        float v[4] = {m.x * inv, m.y * inv, m.z * inv, m.w * inv};
        size_t base = (size_t)g * D + t * 4;
        *(float4*)(g_a + base) = make_float4(v[0], v[1], v[2], v[3]);
#pragma unroll
        for (int i = 0; i < 4; i++) g_Ah[base + i] = __float2half_rn(v[i]);
    } else {
        // ---- B side: inv-norm + fp16 cast (padded) ----
        int row = blockIdx.x - WGRP;
        size_t base = (size_t)row * D + t * 4;
        if (row < TB) {
            float4 v4 = *(const float4*)(tb + base);
            float v[4] = {v4.x, v4.y, v4.z, v4.w};
            float ss = v[0] * v[0] + v[1] * v[1] + v[2] * v[2] + v[3] * v[3];
#pragma unroll
            for (int o = 16; o > 0; o >>= 1) ss += __shfl_xor_sync(0xffffffffu, ss, o);
            __shared__ float wsum[4];
            if ((t & 31) == 0) wsum[t >> 5] = ss;
            __syncthreads();
            float tot = wsum[0] + wsum[1] + wsum[2] + wsum[3];
            if (t == 0) g_invt[row] = 1.0f / fmaxf(sqrtf(tot), 1e-8f);
#pragma unroll
            for (int i = 0; i < 4; i++) g_Bh[base + i] = __float2half_rn(v[i]);
        } else {
            __half z = __float2half_rn(0.0f);
            if (t == 0) g_invt[row] = 0.0f;
#pragma unroll
            for (int i = 0; i < 4; i++) g_Bh[base + i] = z;
        }
    }
}

// ---------------- Kernel C: fp16 HMMA GEMM, single-barrier multistage mainloop ----------------
__global__ __launch_bounds__(256, 2)
void k_gemm() {
    extern __shared__ char dsm[];
    __shared__ float sInv[128];
    __shared__ float smax[128][4];

    const int tid = threadIdx.x;
    const int wid = tid >> 5, lane = tid & 31;
    const int wr = wid >> 2, wc = wid & 3;
    const int rowblk = blockIdx.x, coltile = blockIdx.y;

    if (tid < 128) sInv[tid] = g_invt[coltile * 128 + tid];

    const uint32_t sbase = smem_u32(dsm);

    const int r0 = tid >> 3;
    const int cch = tid & 7;
    const __half* gA = g_Ah + (size_t)(rowblk * 128 + r0) * D + cch * 8;
    const __half* gB = g_Bh + (size_t)(coltile * 128 + r0) * D + cch * 8;

    auto load_chunk = [&](int c, int buf) {
        uint32_t st = sbase + buf * STAGE_B;
        const __half* a = gA + c * BK;
        const __half* b = gB + c * BK;
#pragma unroll
        for (int i = 0; i < 4; i++) {
            int row = r0 + 32 * i;
            uint32_t soff = (uint32_t)row * 128 + ((uint32_t)(cch ^ (row & 7))) * 16;
            cp16(st + soff, a + (size_t)(32 * i) * D);
            cp16(st + PLANE_B + soff, b + (size_t)(32 * i) * D);
        }
        cp_commit();
    };

    load_chunk(0, 0);
    load_chunk(1, 1);

    float acc[4][4][4];
#pragma unroll
    for (int mt = 0; mt < 4; mt++)
#pragma unroll
        for (int nt = 0; nt < 4; nt++)
#pragma unroll
            for (int q = 0; q < 4; q++) acc[mt][nt][q] = 0.0f;

    const int a_m  = wr * 64 + (lane & 15);
    const int a_kh = lane >> 4;
    const int b_n  = wc * 32 + (lane & 7) + ((lane >> 4) & 1) * 8;
    const int b_kh = (lane >> 3) & 1;

    for (int c = 0; c < NCH; c++) {
        if (c < NCH - 1) cp_wait<1>(); else cp_wait<0>();
        __syncthreads();
        if (c + 2 < NCH) load_chunk(c + 2, (c + 2) % 3);

        const uint32_t st = sbase + (c % 3) * STAGE_B;
#pragma unroll
        for (int ks = 0; ks < 4; ks++) {
            uint32_t af[4][4];
#pragma unroll
            for (int mt = 0; mt < 4; mt++) {
                int m = a_m + mt * 16;
                uint32_t chunk = (uint32_t)(ks * 2 + a_kh);
                ldsm_x4(af[mt], st + (uint32_t)m * 128 + (chunk ^ (m & 7)) * 16);
            }
            uint32_t bf[8];
#pragma unroll
            for (int ntp = 0; ntp < 2; ntp++) {
                int n = b_n + ntp * 16;
                uint32_t chunk = (uint32_t)(ks * 2 + b_kh);
                uint32_t r4[4];
                ldsm_x4(r4, st + PLANE_B + (uint32_t)n * 128 + (chunk ^ (n & 7)) * 16);
                bf[ntp * 4 + 0] = r4[0]; bf[ntp * 4 + 1] = r4[1];
                bf[ntp * 4 + 2] = r4[2]; bf[ntp * 4 + 3] = r4[3];
            }
#pragma unroll
            for (int mt = 0; mt < 4; mt++)
#pragma unroll
                for (int nt = 0; nt < 4; nt++)
                    mma16816(acc[mt][nt], af[mt], &bf[nt * 2]);
        }
    }
    __syncthreads();

    // ---- epilogue: scale, store fp16, and per-row tile max ----
    const int rb = wr * 64 + (lane >> 2);
    const int cb = wc * 32 + (lane & 3) * 2;
    const size_t grow0 = (size_t)(rowblk * 128);
    const int gcol0 = coltile * 128;

    float rmaxA[4], rmaxB[4];
#pragma unroll
    for (int mt = 0; mt < 4; mt++) { rmaxA[mt] = -1e30f; rmaxB[mt] = -1e30f; }

#pragma unroll
    for (int mt = 0; mt < 4; mt++) {
#pragma unroll
        for (int nt = 0; nt < 4; nt++) {
            int r = rb + mt * 16, cc = cb + nt * 8;
            int gc0 = gcol0 + cc, gc1 = gc0 + 1;
            float i0 = sInv[cc], i1 = sInv[cc + 1];
            float v0 = acc[mt][nt][0] * i0, v1 = acc[mt][nt][1] * i1;
            float v2 = acc[mt][nt][2] * i0, v3 = acc[mt][nt][3] * i1;
            *(__half2*)&g_cos[(grow0 + r)     * TBP + gc0] = __floats2half2_rn(v0, v1);
            *(__half2*)&g_cos[(grow0 + r + 8) * TBP + gc0] = __floats2half2_rn(v2, v3);
            float m0 = (gc0 < TB) ? v0 : -1e30f;
            float m1 = (gc1 < TB) ? v1 : -1e30f;
            float m2 = (gc0 < TB) ? v2 : -1e30f;
            float m3 = (gc1 < TB) ? v3 : -1e30f;
            rmaxA[mt] = fmaxf(rmaxA[mt], fmaxf(m0, m1));
            rmaxB[mt] = fmaxf(rmaxB[mt], fmaxf(m2, m3));
        }
    }
#pragma unroll
    for (int o = 1; o <= 2; o <<= 1) {
#pragma unroll
        for (int mt = 0; mt < 4; mt++) {
            rmaxA[mt] = fmaxf(rmaxA[mt], __shfl_xor_sync(0xffffffffu, rmaxA[mt], o));
            rmaxB[mt] = fmaxf(rmaxB[mt], __shfl_xor_sync(0xffffffffu, rmaxB[mt], o));
        }
    }
    if ((lane & 3) == 0) {
        int rr = wr * 64 + (lane >> 2);
#pragma unroll
        for (int mt = 0; mt < 4; mt++) {
            smax[rr + mt * 16][wc]     = rmaxA[mt];
            smax[rr + mt * 16 + 8][wc] = rmaxB[mt];
        }
    }
    __syncthreads();
    if (tid < 128) {
        float m = fmaxf(fmaxf(smax[tid][0], smax[tid][1]), fmaxf(smax[tid][2], smax[tid][3]));
        g_tmax[(grow0 + tid) * NCT + coltile] = m;
    }
}

// ---------------- Kernel D: select with tight margin + no-rescore fast path ----------------
__global__ __launch_bounds__(128)
void k_select(const float* __restrict__ tb) {
    const int row = blockIdx.x, t = threadIdx.x;
    const int lane = t & 31, w = t >> 5;

    __shared__ float  s_red[4][5];
    __shared__ int    s_redi[4][5];
    __shared__ int    s_t5[5];
    __shared__ float  s_thresh;
    __shared__ int    s_ntile, s_cnt;
    __shared__ int    s_tiles[MAXTILE];
    __shared__ int    s_cand[MAXCAND];
    __shared__ double s_cval[MAXCAND];
    __shared__ int    s_sel[KTOP];

    // ---- phase 1: load tmax (regs) + per-warp lex top-5 ----
    const float* tmrow = g_tmax + (size_t)row * NCT;
    float tm0 = (t < NCT) ? tmrow[t] : -1e30f;
    float tm1 = (t + 128 < NCT) ? tmrow[t + 128] : -1e30f;
    {
        float v0 = tm0, v1 = tm1;
        int   i0 = t,   i1 = t + 128;
#pragma unroll
        for (int s = 0; s < KTOP; s++) {
            float bv; int bc;
            if (v0 > v1 || (v0 == v1 && i0 < i1)) { bv = v0; bc = i0; }
            else                                   { bv = v1; bc = i1; }
#pragma unroll
            for (int o = 16; o > 0; o >>= 1) {
                float ov = __shfl_xor_sync(0xffffffffu, bv, o);
                int   oc = __shfl_xor_sync(0xffffffffu, bc, o);
                if (ov > bv || (ov == bv && oc < bc)) { bv = ov; bc = oc; }
            }
            if (lane == 0) { s_red[w][s] = bv; s_redi[w][s] = bc; }
            if (i0 == bc) v0 = -1e30f;
            if (i1 == bc) v1 = -1e30f;
        }
    }
    if (t == 0) { s_ntile = 0; s_cnt = 0; }
    __syncthreads();

    // ---- phase 1b: warp 0 merges 4x5 entries -> top-5 tiles ----
    if (w == 0) {
        float v = (lane < 20) ? s_red[lane / 5][lane % 5] : -1e30f;
        int   c = (lane < 20) ? s_redi[lane / 5][lane % 5] : 0x7fffffff;
#pragma unroll
        for (int s = 0; s < KTOP; s++) {
            float bv = v; int bc = c;
#pragma unroll
            for (int o = 16; o > 0; o >>= 1) {
                float ov = __shfl_xor_sync(0xffffffffu, bv, o);
                int   oc = __shfl_xor_sync(0xffffffffu, bc, o);
                if (ov > bv || (ov == bv && oc < bc)) { bv = ov; bc = oc; }
            }
            if (lane == 0) s_t5[s] = bc;
            if (c == bc) v = -1e30f;
        }
    }
    __syncthreads();

    // ---- phase 2: scan the 5 best tiles -> v5 (5th-largest stored) ----
    const __half* crow = g_cos + (size_t)row * TBP;
    {
        float tv[5] = {-1e30f, -1e30f, -1e30f, -1e30f, -1e30f};
#pragma unroll
        for (int r = 0; r < 5; r++) {
            int col = s_t5[r] * 128 + t;
            float v = (col < TB) ? __half2float(crow[col]) : -1e30f;
            ins5v(tv, v);
        }
#pragma unroll
        for (int o = 16; o > 0; o >>= 1) {
            float ov[5];
#pragma unroll
            for (int q = 0; q < 5; q++) ov[q] = __shfl_xor_sync(0xffffffffu, tv[q], o);
#pragma unroll
            for (int q = 0; q < 5; q++) ins5v(tv, ov[q]);
        }
        if (lane == 0) {
#pragma unroll
            for (int q = 0; q < 5; q++) s_red[w][q] = tv[q];
        }
    }
    __syncthreads();
    if (t == 0) {
        float mv[5] = {-1e30f, -1e30f, -1e30f, -1e30f, -1e30f};
#pragma unroll
        for (int ww = 0; ww < 4; ww++)
#pragma unroll
            for (int q = 0; q < 5; q++) ins5v(mv, s_red[ww][q]);
        s_thresh = mv[4] - MARGIN;
    }
    __syncthreads();
    const float thresh = s_thresh;

    // ---- phase 3: qualifying tiles from registers ----
    if (tm0 >= thresh) {
        int p = atomicAdd(&s_ntile, 1);
        if (p < MAXTILE) s_tiles[p] = t;
    }
    if (tm1 >= thresh) {
        int p = atomicAdd(&s_ntile, 1);
        if (p < MAXTILE) s_tiles[p] = t + 128;
    }
    __syncthreads();
    const int ntile = min(s_ntile, MAXTILE);

    // ---- phase 4: scan qualifying tiles for candidates ----
    for (int j = t; j < ntile * 128; j += 128) {
        int col = s_tiles[j >> 7] * 128 + (j & 127);
        if (col < TB) {
            float v = __half2float(crow[col]);
            if (v >= thresh) {
                int p = atomicAdd(&s_cnt, 1);
                if (p < MAXCAND) s_cand[p] = col;
            }
        }
    }
    __syncthreads();
    const int ncand = min(s_cnt, MAXCAND);

    if (ncand > KTOP) {
        // ---- phase 5: exact rescore (double), warp per candidate ----
        const float* arow = g_a + (size_t)row * D;
        for (int ci = w; ci < ncand; ci += 4) {
            int c = s_cand[ci];
            const float* trow = tb + (size_t)c * D;
            double acc = 0.0;
#pragma unroll
            for (int j = 0; j < 16; j++) {
                int idx = lane + 32 * j;
                acc += (double)arow[idx] * (double)trow[idx];
            }
#pragma unroll
            for (int o = 16; o > 0; o >>= 1) acc += __shfl_xor_sync(0xffffffffu, acc, o);
            if (lane == 0) s_cval[ci] = acc * (double)g_invt[c];
        }
        __syncthreads();

        // ---- phase 6: warp-0 butterfly lex top-5 ----
        if (w == 0) {
            double v0 = (lane < ncand) ? s_cval[lane] : -1e300;
            int    c0 = (lane < ncand) ? s_cand[lane] : 0x7fffffff;
            double v1 = (lane + 32 < ncand) ? s_cval[lane + 32] : -1e300;
            int    c1 = (lane + 32 < ncand) ? s_cand[lane + 32] : 0x7fffffff;
#pragma unroll
            for (int s = 0; s < KTOP; s++) {
                double bv; int bc;
                if (v0 > v1 || (v0 == v1 && c0 < c1)) { bv = v0; bc = c0; }
                else                                  { bv = v1; bc = c1; }
#pragma unroll
                for (int o = 16; o > 0; o >>= 1) {
                    double ov = __shfl_xor_sync(0xffffffffu, bv, o);
                    int    oc = __shfl_xor_sync(0xffffffffu, bc, o);
                    if (ov > bv || (ov == bv && oc < bc)) { bv = ov; bc = oc; }
                }
                if (lane == 0) s_sel[s] = bc;
                if (c0 == bc) v0 = -1e300;
                if (c1 == bc) v1 = -1e300;
            }
        }
    } else {
        // ---- fast path: exactly 5 candidates -> they ARE the true top-5 set ----
        if (t < KTOP) s_sel[t] = s_cand[t];
    }
    __syncthreads();

    // ---- phase 7: gather + mean (128 threads, float4) ----
    int c0 = s_sel[0], c1 = s_sel[1], c2 = s_sel[2], c3 = s_sel[3], c4 = s_sel[4];
    {
        int idx = t * 4;
        float4 v0 = *(const float4*)(tb + (size_t)c0 * D + idx);
        float4 v1 = *(const float4*)(tb + (size_t)c1 * D + idx);
        float4 v2 = *(const float4*)(tb + (size_t)c2 * D + idx);
        float4 v3 = *(const float4*)(tb + (size_t)c3 * D + idx);
        float4 v4 = *(const float4*)(tb + (size_t)c4 * D + idx);
        float4 s;
        s.x = (v0.x + v1.x + v2.x + v3.x + v4.x) * 0.2f;
        s.y = (v0.y + v1.y + v2.y + v3.y + v4.y) * 0.2f;
        s.z = (v0.z + v1.z + v2.z + v3.z + v4.z) * 0.2f;
        s.w = (v0.w + v1.w + v2.w + v3.w + v4.w) * 0.2f;
        *(float4*)(g_topk + (size_t)row * D + idx) = s;
    }
}

// ---------------- Kernel E: out = topk_avg @ W^T + b (packed f32x2 FMA) ----------------
__global__ __launch_bounds__(256)
void k_out(const float* __restrict__ W, const float* __restrict__ bias, float* __restrict__ out) {
    __shared__ float As[16][68];
    __shared__ float Ws[16][68];
    int tid = threadIdx.x;
    int tx = tid & 15, ty = tid >> 4;
    int r0 = blockIdx.x * 64, o0 = blockIdx.y * 64;
    int lr = tid >> 2, k4 = tid & 3;
    const float* Ap = g_topk + (size_t)(r0 + lr) * D + k4 * 4;
    const float* Wp = W + (size_t)(o0 + lr) * D + k4 * 4;
    ull acc2[4][2];
#pragma unroll
    for (int i = 0; i < 4; i++) { acc2[i][0] = 0ull; acc2[i][1] = 0ull; }
    float4 ra = *(const float4*)Ap;
    float4 rw = *(const float4*)Wp;
    for (int kb = 0; kb < 32; kb++) {
        As[k4 * 4 + 0][lr] = ra.x; As[k4 * 4 + 1][lr] = ra.y;
        As[k4 * 4 + 2][lr] = ra.z; As[k4 * 4 + 3][lr] = ra.w;
        Ws[k4 * 4 + 0][lr] = rw.x; Ws[k4 * 4 + 1][lr] = rw.y;
        Ws[k4 * 4 + 2][lr] = rw.z; Ws[k4 * 4 + 3][lr] = rw.w;
        __syncthreads();
        if (kb + 1 < 32) {
            ra = *(const float4*)(Ap + (kb + 1) * 16);
            rw = *(const float4*)(Wp + (kb + 1) * 16);
        }
#pragma unroll
        for (int k = 0; k < 16; k++) {
            float4 a = *(const float4*)&As[k][ty * 4];
            float4 w = *(const float4*)&Ws[k][tx * 4];
            ull w01 = pk2(w.x, w.y), w23 = pk2(w.z, w.w);
            float av[4] = {a.x, a.y, a.z, a.w};
#pragma unroll
            for (int i = 0; i < 4; i++) {
                ull ai = pk2(av[i], av[i]);
                fma2(acc2[i][0], ai, w01);
                fma2(acc2[i][1], ai, w23);
            }
        }
        __syncthreads();
    }
#pragma unroll
    for (int i = 0; i < 4; i++) {
        float a0, a1, a2, a3;
        unpk2(acc2[i][0], a0, a1);
        unpk2(acc2[i][1], a2, a3);
        float accr[4] = {a0, a1, a2, a3};
#pragma unroll
        for (int jj = 0; jj < 4; jj++) {
            float bj = bias[o0 + tx * 4 + jj];
            out[(size_t)(r0 + ty * 4 + i) * D + o0 + tx * 4 + jj] = accr[jj] + bj;
        }
    }
}

extern "C" void kernel_launch(void* const* d_in, const int* in_sizes, int n_in,
                              void* d_out, int out_size) {
    const float* x  = (const float*)d_in[0];
    const float* tb = (const float*)d_in[1];
    const float* W  = (const float*)d_in[2];
    const float* b  = (const float*)d_in[3];
    float* out = (float*)d_out;

    cudaFuncSetAttribute(k_gemm, cudaFuncAttributeMaxDynamicSharedMemorySize, DSMEM_TOTAL);

    k_prep<<<WGRP + TBP, 128>>>(x, tb);
    k_gemm<<<dim3(NRT, NCT), 256, DSMEM_TOTAL>>>();
    k_select<<<WGRP, 128>>>(tb);
    k_out<<<dim3(WGRP / 64, D / 64), 256>>>(W, b, out);
}